// round 1
// baseline (speedup 1.0000x reference)
#include <cuda_runtime.h>
#include <cuda_bf16.h>

#define B_ 64
#define F_ 4096
#define E_ 256
#define H_ 512
#define U_ 512

#define BM 128
#define AS_STRIDE 268   // 256 + 12 pad -> conflict-free quad access
#define BS_STRIDE 136   // 128 + 8  pad -> conflict-free quad access

// scratch (allocation-free rule: __device__ globals)
__device__ float g_bias[B_ * U_];     // W1_b[u] + proj_h[b][u]
__device__ float g_scores[B_ * F_];   // pre-softmax scores (V_b dropped: softmax-invariant)

__device__ __forceinline__ float tanh_fast(float x) {
    float y;
    asm("tanh.approx.f32 %0, %1;" : "=f"(y) : "f"(x));
    return y;
}
__device__ __forceinline__ float to_tf32(float x) {
    float y;
    asm("cvt.rna.tf32.f32 %0, %1;" : "=f"(y) : "f"(x));
    return y;
}
__device__ __forceinline__ void mma_tf32(float* c, const unsigned* a, unsigned b0, unsigned b1) {
    asm volatile(
        "mma.sync.aligned.m16n8k8.row.col.f32.tf32.tf32.f32 "
        "{%0,%1,%2,%3}, {%4,%5,%6,%7}, {%8,%9}, {%0,%1,%2,%3};"
        : "+f"(c[0]), "+f"(c[1]), "+f"(c[2]), "+f"(c[3])
        : "r"(a[0]), "r"(a[1]), "r"(a[2]), "r"(a[3]), "r"(b0), "r"(b1));
}

// ---------------------------------------------------------------------------
// K1: g_bias[b][u] = W1_b[u] + W2_b[u] + sum_h hidden[b][h] * W2[h][u]
// ---------------------------------------------------------------------------
__global__ __launch_bounds__(512) void bias_kernel(
    const float* __restrict__ hidden, const float* __restrict__ W2w,
    const float* __restrict__ W2b, const float* __restrict__ W1b)
{
    __shared__ float hs[H_];
    int b = blockIdx.x;
    int u = threadIdx.x;
    hs[u] = hidden[b * H_ + u];
    __syncthreads();
    float s = W2b[u];
#pragma unroll 8
    for (int h = 0; h < H_; ++h)
        s += hs[h] * W2w[h * U_ + u];
    g_bias[b * U_ + u] = s + W1b[u];
}

// ---------------------------------------------------------------------------
// K2: fused  scores[r] = sum_u tanh( (features[r,:] @ W1[:,u]) + bias[b][u] ) * V[u]
// Block: 128 rows (one b), 256 threads = 8 warps in 4(m) x 2(n) grid.
// A (features rows) staged once as tf32; W1 streamed in 32x128 k-slices,
// U covered in 4 chunks of 128.
// ---------------------------------------------------------------------------
__global__ __launch_bounds__(256, 1) void fused_score_kernel(
    const float* __restrict__ features, const float* __restrict__ W1w,
    const float* __restrict__ Vw)
{
    extern __shared__ float sm[];
    float* As    = sm;                      // 128 x 268
    float* Bs    = As + BM * AS_STRIDE;     // 32 x 136
    float* sred  = Bs + 32 * BS_STRIDE;     // 128 row partials
    float* biasS = sred + 128;              // 128
    float* vwS   = biasS + 128;             // 128

    const int tid  = threadIdx.x;
    const int lane = tid & 31;
    const int warp = tid >> 5;
    const int wm   = (warp & 3) * 32;       // warp m-offset
    const int wn   = (warp >> 2) * 64;      // warp n-offset within chunk
    const int row0 = blockIdx.x * BM;
    const int b    = row0 >> 12;            // /4096 (BM divides F)

    // Stage A tile (128 x 256) as tf32, coalesced
    const float* fbase = features + (long long)row0 * E_;
#pragma unroll
    for (int idx = tid; idx < BM * E_; idx += 256) {
        int r = idx >> 8, c = idx & 255;
        As[r * AS_STRIDE + c] = to_tf32(fbase[r * E_ + c]);
    }
    if (tid < BM) sred[tid] = 0.f;

    const int q = lane >> 2;       // 0..7
    const int t4 = lane & 3;       // 0..3

    for (int nc = 0; nc < 4; ++nc) {
        const int n0 = nc * 128;
        __syncthreads();  // A staged / biasS free from previous epilogue
        if (tid < 128) {
            biasS[tid] = g_bias[b * U_ + n0 + tid];
            vwS[tid]   = Vw[n0 + tid];
        }

        float acc[2][8][4];
#pragma unroll
        for (int mt = 0; mt < 2; ++mt)
#pragma unroll
            for (int nt = 0; nt < 8; ++nt)
#pragma unroll
                for (int j = 0; j < 4; ++j) acc[mt][nt][j] = 0.f;

        for (int ks = 0; ks < 8; ++ks) {
            __syncthreads();  // previous slice consumed
#pragma unroll
            for (int idx = tid; idx < 32 * 128; idx += 256) {
                int kk = idx >> 7, nn = idx & 127;
                Bs[kk * BS_STRIDE + nn] = to_tf32(W1w[(ks * 32 + kk) * U_ + n0 + nn]);
            }
            __syncthreads();

#pragma unroll
            for (int kk8 = 0; kk8 < 4; ++kk8) {
                const int ak = ks * 32 + kk8 * 8 + t4;   // abs k col in As
                const int bk = kk8 * 8 + t4;             // k row in Bs
                unsigned a[2][4];
#pragma unroll
                for (int mt = 0; mt < 2; ++mt) {
                    int r = wm + mt * 16 + q;
                    a[mt][0] = __float_as_uint(As[r * AS_STRIDE + ak]);
                    a[mt][1] = __float_as_uint(As[(r + 8) * AS_STRIDE + ak]);
                    a[mt][2] = __float_as_uint(As[r * AS_STRIDE + ak + 4]);
                    a[mt][3] = __float_as_uint(As[(r + 8) * AS_STRIDE + ak + 4]);
                }
#pragma unroll
                for (int nt = 0; nt < 8; ++nt) {
                    int cb = wn + nt * 8 + q;
                    unsigned b0 = __float_as_uint(Bs[bk * BS_STRIDE + cb]);
                    unsigned b1 = __float_as_uint(Bs[(bk + 4) * BS_STRIDE + cb]);
                    mma_tf32(acc[0][nt], a[0], b0, b1);
                    mma_tf32(acc[1][nt], a[1], b0, b1);
                }
            }
        }

        // Epilogue: tanh + dot V, reduce per row (biasS visible via loop syncs)
#pragma unroll
        for (int mt = 0; mt < 2; ++mt) {
            float p0 = 0.f, p1 = 0.f;
            int r = wm + mt * 16 + q;
#pragma unroll
            for (int nt = 0; nt < 8; ++nt) {
                int c = wn + nt * 8 + t4 * 2;
                float bb0 = biasS[c], bb1 = biasS[c + 1];
                float v0 = vwS[c], v1 = vwS[c + 1];
                p0 += tanh_fast(acc[mt][nt][0] + bb0) * v0
                    + tanh_fast(acc[mt][nt][1] + bb1) * v1;
                p1 += tanh_fast(acc[mt][nt][2] + bb0) * v0
                    + tanh_fast(acc[mt][nt][3] + bb1) * v1;
            }
            atomicAdd(&sred[r], p0);
            atomicAdd(&sred[r + 8], p1);
        }
    }

    __syncthreads();
    if (tid < BM) g_scores[row0 + tid] = sred[tid];
}

// ---------------------------------------------------------------------------
// K3: softmax over F per batch. 64 blocks x 256 threads, 16 elems/thread.
// ---------------------------------------------------------------------------
__global__ __launch_bounds__(256) void softmax_kernel(float* __restrict__ out_w)
{
    const int b = blockIdx.x, tid = threadIdx.x;
    const float* s = g_scores + b * F_;
    float loc[16];
    float m = -1e30f;
#pragma unroll
    for (int i = 0; i < 16; ++i) {
        loc[i] = s[i * 256 + tid];
        m = fmaxf(m, loc[i]);
    }
    __shared__ float redm[8], reds[8];
#pragma unroll
    for (int o = 16; o > 0; o >>= 1) m = fmaxf(m, __shfl_xor_sync(0xffffffffu, m, o));
    if ((tid & 31) == 0) redm[tid >> 5] = m;
    __syncthreads();
    m = redm[0];
#pragma unroll
    for (int i = 1; i < 8; ++i) m = fmaxf(m, redm[i]);

    float sum = 0.f;
#pragma unroll
    for (int i = 0; i < 16; ++i) {
        loc[i] = __expf(loc[i] - m);
        sum += loc[i];
    }
#pragma unroll
    for (int o = 16; o > 0; o >>= 1) sum += __shfl_xor_sync(0xffffffffu, sum, o);
    if ((tid & 31) == 0) reds[tid >> 5] = sum;
    __syncthreads();
    sum = 0.f;
#pragma unroll
    for (int i = 0; i < 8; ++i) sum += reds[i];
    float inv = 1.f / sum;
#pragma unroll
    for (int i = 0; i < 16; ++i)
        out_w[b * F_ + i * 256 + tid] = loc[i] * inv;
}

// ---------------------------------------------------------------------------
// K4: context[b][e] = sum_f w[b][f] * features[b][f][e]
// ---------------------------------------------------------------------------
__global__ void zero_ctx(float* __restrict__ ctx)
{
    ctx[blockIdx.x * 256 + threadIdx.x] = 0.f;
}

__global__ __launch_bounds__(256) void context_kernel(
    const float* __restrict__ features, const float* __restrict__ w,
    float* __restrict__ ctx)
{
    __shared__ float ws[256];
    const int b = blockIdx.y;
    const int f0 = blockIdx.x * 256;
    const int tid = threadIdx.x;
    ws[tid] = w[b * F_ + f0 + tid];
    __syncthreads();
    const float* fp = features + (long long)(b * F_ + f0) * E_ + tid;
    float acc = 0.f;
#pragma unroll 8
    for (int i = 0; i < 256; ++i)
        acc += ws[i] * fp[(long long)i * E_];
    atomicAdd(&ctx[b * E_ + tid], acc);
}

// ---------------------------------------------------------------------------
extern "C" void kernel_launch(void* const* d_in, const int* in_sizes, int n_in,
                              void* d_out, int out_size)
{
    const float* features = (const float*)d_in[0];
    const float* hidden   = (const float*)d_in[1];
    const float* W1w      = (const float*)d_in[2];
    const float* W1b      = (const float*)d_in[3];
    const float* W2w      = (const float*)d_in[4];
    const float* W2b      = (const float*)d_in[5];
    const float* Vw       = (const float*)d_in[6];
    // d_in[7] = V_b: constant shift of scores -> cancels in softmax; scores not output.

    float* out  = (float*)d_out;
    float* ctx  = out;              // (64, 256)
    float* wout = out + B_ * E_;    // (64, 4096, 1)

    bias_kernel<<<B_, 512>>>(hidden, W2w, W2b, W1b);

    const size_t smem_bytes =
        (size_t)(BM * AS_STRIDE + 32 * BS_STRIDE + 3 * 128) * sizeof(float);
    cudaFuncSetAttribute(fused_score_kernel,
                         cudaFuncAttributeMaxDynamicSharedMemorySize,
                         (int)smem_bytes);
    fused_score_kernel<<<(B_ * F_) / BM, 256, smem_bytes>>>(features, W1w, Vw);

    softmax_kernel<<<B_, 256>>>(wout);

    zero_ctx<<<B_, 256>>>(ctx);
    context_kernel<<<dim3(F_ / 256, B_), 256>>>(features, wout, ctx);
}

// round 4
// speedup vs baseline: 2.5165x; 2.5165x over previous
#include <cuda_runtime.h>
#include <cuda_fp16.h>
#include <cstdint>

#define B_ 64
#define F_ 4096
#define E_ 256
#define H_ 512
#define U_ 512

// ---------------- scratch (__device__ globals: allocation-free rule) -------
__device__ float  g_bias[B_ * U_];     // W1_b[u] + W2_b[u] + hidden@W2
__device__ float  g_scores[B_ * F_];   // pre-softmax scores (V_b dropped: softmax-invariant)
__device__ __half g_W1Th[U_ * E_];     // W1 transposed (u-major, e contiguous) as fp16

__device__ __forceinline__ float tanh_fast(float x) {
    float y; asm("tanh.approx.f32 %0, %1;" : "=f"(y) : "f"(x)); return y;
}
__device__ __forceinline__ uint32_t smem_u32(const void* p) {
    uint32_t a;
    asm("{ .reg .u64 t; cvta.to.shared.u64 t, %1; cvt.u32.u64 %0, t; }" : "=r"(a) : "l"(p));
    return a;
}

#define LDM_X4(r0, r1, r2, r3, addr) \
    asm volatile("ldmatrix.sync.aligned.m8n8.x4.shared.b16 {%0,%1,%2,%3}, [%4];" \
        : "=r"(r0), "=r"(r1), "=r"(r2), "=r"(r3) : "r"(addr))

__device__ __forceinline__ void mma_f16(float* c, const uint32_t* a,
                                        uint32_t b0, uint32_t b1) {
    asm volatile(
        "mma.sync.aligned.m16n8k16.row.col.f32.f16.f16.f32 "
        "{%0,%1,%2,%3}, {%4,%5,%6,%7}, {%8,%9}, {%0,%1,%2,%3};"
        : "+f"(c[0]), "+f"(c[1]), "+f"(c[2]), "+f"(c[3])
        : "r"(a[0]), "r"(a[1]), "r"(a[2]), "r"(a[3]), "r"(b0), "r"(b1));
}

// ---------------- smem layout for K2 (halves / floats, byte offsets) -------
#define LDA 264                    // halves per A row (256 + 8 pad) -> 528B, 33*16B
#define LDB 72                     // halves per B row (64 + 8 pad)  -> 144B,  9*16B
#define OFF_AS   0                 // 128 * 528  = 67584 B
#define OFF_BS   67584             // 128 * 144  = 18432 B
#define OFF_BIAS 86016             // 512 floats = 2048 B
#define OFF_VW   88064             // 512 floats = 2048 B
#define OFF_SRED 90112             // 128 floats = 512 B
#define SMEM_K2  90624

// ---------------------------------------------------------------------------
// K0: zero context (output poisoned to 0xAA; K4 accumulates with atomics)
// ---------------------------------------------------------------------------
__global__ void zero_ctx(float* __restrict__ ctx)
{
    ctx[blockIdx.x * 256 + threadIdx.x] = 0.f;
}

// ---------------------------------------------------------------------------
// K1: g_bias[b][u] = W1_b[u] + W2_b[u] + sum_h hidden[b][h] * W2[h][u]
// ---------------------------------------------------------------------------
__global__ __launch_bounds__(512) void bias_kernel(
    const float* __restrict__ hidden, const float* __restrict__ W2w,
    const float* __restrict__ W2b, const float* __restrict__ W1b)
{
    __shared__ float hs[H_];
    int b = blockIdx.x;
    int u = threadIdx.x;
    hs[u] = hidden[b * H_ + u];
    __syncthreads();
    float s = W2b[u];
#pragma unroll 8
    for (int h = 0; h < H_; ++h)
        s += hs[h] * W2w[h * U_ + u];
    g_bias[b * U_ + u] = s + W1b[u];
}

// ---------------------------------------------------------------------------
// K1b: transpose + fp16-convert W1 (E,U) -> g_W1Th (U,E)
// ---------------------------------------------------------------------------
__global__ __launch_bounds__(1024) void transpose_w1(const float* __restrict__ W1w)
{
    __shared__ float t[32][33];
    int u0 = blockIdx.x * 32, e0 = blockIdx.y * 32;
    int tx = threadIdx.x & 31, ty = threadIdx.x >> 5;
    t[ty][tx] = W1w[(e0 + ty) * U_ + u0 + tx];
    __syncthreads();
    g_W1Th[(u0 + ty) * E_ + e0 + tx] = __float2half_rn(t[tx][ty]);
}

// ---------------------------------------------------------------------------
// K2: fused fp16 register-MMA GEMM + tanh + dot(V) -> scores
// CTA: M=128 rows (A resident in smem, fp16), loops 4 U-chunks of N=128,
//      K=256 streamed for B in 4 slices of 64.
// 8 warps = 4(m) x 2(n); warp tile 32m x 64n; mma m16n8k16 f16.f32.
// ---------------------------------------------------------------------------
__global__ __launch_bounds__(256, 2) void fused_score_mma(
    const float* __restrict__ features, const float* __restrict__ Vw)
{
    extern __shared__ char smem[];
    const uint32_t sb = smem_u32(smem);

    const int tid  = threadIdx.x;
    const int lane = tid & 31;
    const int warp = tid >> 5;
    const int q    = lane >> 2;          // 0..7
    const int t4   = lane & 3;           // 0..3
    const int wm   = (warp & 3) * 32;
    const int wn   = (warp >> 2) * 64;
    const int r0   = blockIdx.x * 128;   // flattened (b,f) row base
    const int b    = r0 >> 12;

    float* biasS = (float*)(smem + OFF_BIAS);
    float* vwS   = (float*)(smem + OFF_VW);
    float* sred  = (float*)(smem + OFF_SRED);

    // ---- prologue: bias/V, zero sred, stage A (fp32 -> fp16, row-major) ----
    {
        biasS[tid]       = g_bias[b * U_ + tid];
        biasS[tid + 256] = g_bias[b * U_ + tid + 256];
        vwS[tid]         = Vw[tid];
        vwS[tid + 256]   = Vw[tid + 256];
        if (tid < 128) sred[tid] = 0.f;

        const int row = tid >> 1;
        const int kh  = (tid & 1) * 128;
        const float4* src =
            (const float4*)(features + (size_t)(r0 + row) * E_ + kh);
        char* dst = smem + OFF_AS + row * (LDA * 2) + kh * 2;
#pragma unroll 8
        for (int j = 0; j < 32; ++j) {
            float4 v = src[j];
            __half2 h0 = __floats2half2_rn(v.x, v.y);
            __half2 h1 = __floats2half2_rn(v.z, v.w);
            uint2 pk = make_uint2(*(uint32_t*)&h0, *(uint32_t*)&h1);
            *(uint2*)(dst + j * 8) = pk;
        }
    }
    __syncthreads();

    // per-thread ldmatrix addresses
    uint32_t aAddr[2];
#pragma unroll
    for (int mt = 0; mt < 2; ++mt)
        aAddr[mt] = sb + OFF_AS + (wm + mt * 16 + (lane & 15)) * (LDA * 2)
                       + ((lane >> 4) * 8) * 2;
    const uint32_t bAddr = sb + OFF_BS
        + (wn + ((lane >> 4) & 1) * 8 + (lane & 7)) * (LDB * 2)
        + ((lane >> 3) & 1) * 16;

    // B staging: each thread owns 32 halves of a B row (4 x 16B)
    const int bn  = tid >> 1;
    const int bkh = (tid & 1) * 32;
    const uint32_t bStore = sb + OFF_BS + bn * (LDB * 2) + bkh * 2;

    for (int uq = 0; uq < 4; ++uq) {
        const int u0 = uq * 128;

        float acc[2][8][4];
#pragma unroll
        for (int mt = 0; mt < 2; ++mt)
#pragma unroll
            for (int nt = 0; nt < 8; ++nt)
#pragma unroll
                for (int j = 0; j < 4; ++j) acc[mt][nt][j] = 0.f;

        // prefetch B stage 0 (32 halves = 4 x uint4)
        uint4 pre[4];
        {
            const uint4* bsrc =
                (const uint4*)(g_W1Th + (size_t)(u0 + bn) * E_ + bkh);
#pragma unroll
            for (int j = 0; j < 4; ++j) pre[j] = bsrc[j];
        }

        for (int ks = 0; ks < 4; ++ks) {
            __syncthreads();                 // Bs free
#pragma unroll
            for (int j = 0; j < 4; ++j)
                asm volatile("st.shared.v4.b32 [%0], {%1,%2,%3,%4};" ::
                    "r"(bStore + j * 16),
                    "r"(pre[j].x), "r"(pre[j].y), "r"(pre[j].z), "r"(pre[j].w));
            __syncthreads();                 // Bs ready
            if (ks < 3) {
                const uint4* nsrc =
                    (const uint4*)(g_W1Th + (size_t)(u0 + bn) * E_ + (ks + 1) * 64 + bkh);
#pragma unroll
                for (int j = 0; j < 4; ++j) pre[j] = nsrc[j];
            }

#pragma unroll
            for (int kk = 0; kk < 4; ++kk) {
                const int k0 = ks * 64 + kk * 16;   // abs k in As
                uint32_t a[2][4];
#pragma unroll
                for (int mt = 0; mt < 2; ++mt)
                    LDM_X4(a[mt][0], a[mt][1], a[mt][2], a[mt][3],
                           aAddr[mt] + k0 * 2);
#pragma unroll
                for (int ntp = 0; ntp < 4; ++ntp) {
                    uint32_t b0, b1, b2, b3;
                    LDM_X4(b0, b1, b2, b3,
                           bAddr + ntp * (16 * LDB * 2) + kk * 32);
                    mma_f16(acc[0][2 * ntp],     a[0], b0, b1);
                    mma_f16(acc[0][2 * ntp + 1], a[0], b2, b3);
                    mma_f16(acc[1][2 * ntp],     a[1], b0, b1);
                    mma_f16(acc[1][2 * ntp + 1], a[1], b2, b3);
                }
            }
        }

        // ---- epilogue for this U-chunk: tanh + dot(V), reduce into sred ----
#pragma unroll
        for (int mt = 0; mt < 2; ++mt) {
            float p0 = 0.f, p1 = 0.f;
#pragma unroll
            for (int nt = 0; nt < 8; ++nt) {
                const int c = u0 + wn + nt * 8 + t4 * 2;
                const float bb0 = biasS[c], bb1 = biasS[c + 1];
                const float v0 = vwS[c],   v1 = vwS[c + 1];
                p0 += tanh_fast(acc[mt][nt][0] + bb0) * v0
                    + tanh_fast(acc[mt][nt][1] + bb1) * v1;
                p1 += tanh_fast(acc[mt][nt][2] + bb0) * v0
                    + tanh_fast(acc[mt][nt][3] + bb1) * v1;
            }
            p0 += __shfl_xor_sync(0xffffffffu, p0, 1);
            p0 += __shfl_xor_sync(0xffffffffu, p0, 2);
            p1 += __shfl_xor_sync(0xffffffffu, p1, 1);
            p1 += __shfl_xor_sync(0xffffffffu, p1, 2);
            if (t4 == 0) {
                atomicAdd(&sred[wm + mt * 16 + q], p0);
                atomicAdd(&sred[wm + mt * 16 + q + 8], p1);
            }
        }
    }

    __syncthreads();
    if (tid < 128) g_scores[r0 + tid] = sred[tid];
}

// ---------------------------------------------------------------------------
// K3: softmax over F per batch
// ---------------------------------------------------------------------------
__global__ __launch_bounds__(256) void softmax_kernel(float* __restrict__ out_w)
{
    const int b = blockIdx.x, tid = threadIdx.x;
    const float* s = g_scores + b * F_;
    float loc[16];
    float m = -1e30f;
#pragma unroll
    for (int i = 0; i < 16; ++i) {
        loc[i] = s[i * 256 + tid];
        m = fmaxf(m, loc[i]);
    }
    __shared__ float redm[8], reds[8];
#pragma unroll
    for (int o = 16; o > 0; o >>= 1) m = fmaxf(m, __shfl_xor_sync(0xffffffffu, m, o));
    if ((tid & 31) == 0) redm[tid >> 5] = m;
    __syncthreads();
    m = redm[0];
#pragma unroll
    for (int i = 1; i < 8; ++i) m = fmaxf(m, redm[i]);

    float sum = 0.f;
#pragma unroll
    for (int i = 0; i < 16; ++i) {
        loc[i] = __expf(loc[i] - m);
        sum += loc[i];
    }
#pragma unroll
    for (int o = 16; o > 0; o >>= 1) sum += __shfl_xor_sync(0xffffffffu, sum, o);
    if ((tid & 31) == 0) reds[tid >> 5] = sum;
    __syncthreads();
    sum = 0.f;
#pragma unroll
    for (int i = 0; i < 8; ++i) sum += reds[i];
    float inv = 1.f / sum;
#pragma unroll
    for (int i = 0; i < 16; ++i)
        out_w[b * F_ + i * 256 + tid] = loc[i] * inv;
}

// ---------------------------------------------------------------------------
// K4: context[b][e] = sum_f w[b][f] * features[b][f][e]
// ---------------------------------------------------------------------------
__global__ __launch_bounds__(256) void context_kernel(
    const float* __restrict__ features, const float* __restrict__ w,
    float* __restrict__ ctx)
{
    __shared__ float ws[256];
    const int b = blockIdx.y;
    const int f0 = blockIdx.x * 256;
    const int tid = threadIdx.x;
    ws[tid] = w[b * F_ + f0 + tid];
    __syncthreads();
    const float* fp = features + (long long)(b * F_ + f0) * E_ + tid;
    float acc = 0.f;
#pragma unroll 8
    for (int i = 0; i < 256; ++i)
        acc += ws[i] * fp[(long long)i * E_];
    atomicAdd(&ctx[b * E_ + tid], acc);
}

// ---------------------------------------------------------------------------
extern "C" void kernel_launch(void* const* d_in, const int* in_sizes, int n_in,
                              void* d_out, int out_size)
{
    const float* features = (const float*)d_in[0];
    const float* hidden   = (const float*)d_in[1];
    const float* W1w      = (const float*)d_in[2];
    const float* W1b      = (const float*)d_in[3];
    const float* W2w      = (const float*)d_in[4];
    const float* W2b      = (const float*)d_in[5];
    const float* Vw       = (const float*)d_in[6];
    // d_in[7] = V_b: constant shift of scores -> cancels in softmax; scores not output.

    float* out  = (float*)d_out;
    float* ctx  = out;              // (64, 256)
    float* wout = out + B_ * E_;    // (64, 4096, 1)

    zero_ctx<<<B_, 256>>>(ctx);
    bias_kernel<<<B_, 512>>>(hidden, W2w, W2b, W1b);
    transpose_w1<<<dim3(U_ / 32, E_ / 32), 1024>>>(W1w);

    cudaFuncSetAttribute(fused_score_mma,
                         cudaFuncAttributeMaxDynamicSharedMemorySize, SMEM_K2);
    fused_score_mma<<<(B_ * F_) / 128, 256, SMEM_K2>>>(features, Vw);

    softmax_kernel<<<B_, 256>>>(wout);
    context_kernel<<<dim3(F_ / 256, B_), 256>>>(features, wout, ctx);
}